// round 1
// baseline (speedup 1.0000x reference)
#include <cuda_runtime.h>

// Depth-of-field scatter-as-gather: out(q) = sum_t w*rgb / (sum_t w + 1e-8)
// w = mask(t) * sat(coc_s - dist_t + 0.5) * sigmoid(4*(disp_s - disp_q))
// coc_s = |lens_effect_b * disp_s|
//
// Tap geometry (dist, mask) is a pure function of LENS=11 -> baked in as
// compile-time constants; dead taps (oy^2+ox^2 > 30) eliminated at compile time.
// sigmoid(4d) == 0.5 + 0.5*tanh(2d): one MUFU.TANH per tap.

#define H_ 1024
#define W_ 1024
#define RAD 5
#define TILE 32
#define SH 42               // TILE + 2*RAD
#define NTHREADS 256

__device__ __forceinline__ float tanh_fast(float x) {
    float y;
    asm("tanh.approx.f32 %0, %1;" : "=f"(y) : "f"(x));
    return y;
}

__global__ __launch_bounds__(NTHREADS) void dof_kernel(
    const float* __restrict__ xin,   // (4, 4, 1024, 1024): r,g,b,disp planes
    const float* __restrict__ le,    // (4,) lens effects
    float* __restrict__ out)         // (4, 3, 1024, 1024)
{
    __shared__ float4 sh[SH * SH];   // (r, g, b, 2*disp)

    const int b  = blockIdx.z;
    const float kh = 0.5f * fabsf(le[b]);      // coc = kh * |2*disp|
    const int tx = threadIdx.x;                 // 0..31
    const int ty = threadIdx.y;                 // 0..7
    const int tid = ty * 32 + tx;
    const int x0 = blockIdx.x * TILE - RAD;
    const int y0 = blockIdx.y * TILE - RAD;

    const float* pr = xin + (size_t)(b * 4 + 0) * (H_ * W_);
    const float* pg = xin + (size_t)(b * 4 + 1) * (H_ * W_);
    const float* pb = xin + (size_t)(b * 4 + 2) * (H_ * W_);
    const float* pd = xin + (size_t)(b * 4 + 3) * (H_ * W_);

    // Cooperative tile load with edge-clamp (matches jnp.pad mode='edge')
    for (int i = tid; i < SH * SH; i += NTHREADS) {
        int ly = i / SH;
        int lx = i - ly * SH;
        int gy = min(max(y0 + ly, 0), H_ - 1);
        int gx = min(max(x0 + lx, 0), W_ - 1);
        int gi = gy * W_ + gx;
        sh[i] = make_float4(pr[gi], pg[gi], pb[gi], 2.0f * pd[gi]);
    }
    __syncthreads();

    // c_t = sqrt(oy^2+ox^2) - 0.5, indexed by n = oy^2+ox^2 (compile-time folded)
    constexpr float CT[31] = {
        -0.5f,       0.5f,        0.91421356f, 0.f,         1.5f,
         1.73606798f, 0.f,        0.f,         2.32842712f, 2.5f,
         2.66227766f, 0.f,        0.f,         3.10555128f, 0.f,
         0.f,         3.5f,       3.62310563f, 3.74264069f, 0.f,
         3.97213595f, 0.f,        0.f,         0.f,         0.f,
         4.5f,        4.59901951f,0.f,         0.f,         4.88516481f,
         0.f };

    const int gx_out = blockIdx.x * TILE + tx;

    #pragma unroll 1
    for (int rr = 0; rr < 4; rr++) {
        const int lyy = ty + rr * 8 + RAD;               // shared row of dest
        const float4* base = &sh[lyy * SH + tx + RAD];
        const float eq = base[0].w;                       // 2*disp at dest
        float nr = 0.f, ng = 0.f, nb = 0.f, dn = 0.f;

        #pragma unroll
        for (int oy = -RAD; oy <= RAD; oy++) {
            #pragma unroll
            for (int ox = -RAD; ox <= RAD; ox++) {
                const int n = oy * oy + ox * ox;
                if (n > 30) continue;                     // disk mask, compile-time
                float4 s = base[oy * SH + ox];            // one LDS.128 per tap
                // sat(coc - dist + 0.5) = sat(kh*|e| - (dist-0.5))
                float w0 = __saturatef(fmaf(kh, fabsf(s.w), -CT[n]));
                // sigmoid(4*(sd - dq)) = 0.5 + 0.5*tanh(e_s - e_q)
                float u  = fmaf(tanh_fast(s.w - eq), 0.5f, 0.5f);
                float w  = w0 * u;
                nr = fmaf(w, s.x, nr);
                ng = fmaf(w, s.y, ng);
                nb = fmaf(w, s.z, nb);
                dn += w;
            }
        }

        float inv = 1.0f / (dn + 1e-8f);
        const int gy_out = blockIdx.y * TILE + ty + rr * 8;
        size_t o = ((size_t)(b * 3) * H_ + gy_out) * W_ + gx_out;
        out[o]                = nr * inv;
        out[o + H_ * W_]      = ng * inv;
        out[o + 2 * H_ * W_]  = nb * inv;
    }
}

extern "C" void kernel_launch(void* const* d_in, const int* in_sizes, int n_in,
                              void* d_out, int out_size) {
    const float* x  = (const float*)d_in[0];   // (4,4,1024,1024) f32
    const float* le = (const float*)d_in[1];   // (4,1) f32
    // d_in[2] (diskernel) and d_in[3] (lens_mask) are pure functions of LENS=11,
    // baked into the kernel as compile-time constants.
    dim3 grid(W_ / TILE, H_ / TILE, 4);
    dim3 blk(32, 8);
    dof_kernel<<<grid, blk>>>(x, le, (float*)d_out);
}

// round 4
// speedup vs baseline: 1.5148x; 1.5148x over previous
#include <cuda_runtime.h>
#include <cstdint>

// Depth-of-field scatter-as-gather.
// out(q) = sum_t w*rgb / (sum_t w + eps)
// w ∝ mask(t) * sat(coc_s - dist_t + 0.5) * sigmoid(4*(disp_s - disp_q))
//
// R4 == R3 resubmission (R3 hit an infra-level container failure, never ran).
//  - V=4 vertical register reuse: one LDS.128 tap serves 4 dest pixels.
//  - scale-invariance fold: weights doubled so w = fma(w0, tanh, w0);
//    eps 1e-8 -> 2e-8 keeps the result exactly equivalent.
//  - packed fma.rn.f32x2 accumulation of {r,g} and {b,den}.

#define H_ 1024
#define W_ 1024
#define RAD 5
#define TILE 32
#define SH 42               // TILE + 2*RAD
#define NTHREADS 256
#define V 4                 // dest pixels per thread (vertical)

__device__ __forceinline__ float tanh_fast(float x) {
    float y;
    asm("tanh.approx.f32 %0, %1;" : "=f"(y) : "f"(x));
    return y;
}
__device__ __forceinline__ uint64_t pk2(float lo, float hi) {
    uint64_t d;
    asm("mov.b64 %0, {%1, %2};" : "=l"(d) : "f"(lo), "f"(hi));
    return d;
}
__device__ __forceinline__ void unpk2(uint64_t d, float& lo, float& hi) {
    asm("mov.b64 {%0, %1}, %2;" : "=f"(lo), "=f"(hi) : "l"(d));
}
__device__ __forceinline__ void fma2(uint64_t& acc, uint64_t a, uint64_t b) {
    asm("fma.rn.f32x2 %0, %1, %2, %3;" : "=l"(acc) : "l"(a), "l"(b), "l"(acc));
}

__global__ __launch_bounds__(NTHREADS) void dof_kernel(
    const float* __restrict__ xin,   // (4, 4, 1024, 1024): r,g,b,disp planes
    const float* __restrict__ le,    // (4,) lens effects
    float* __restrict__ out)         // (4, 3, 1024, 1024)
{
    __shared__ float4 sh[SH * SH];   // (r, g, b, 2*disp)

    const int b  = blockIdx.z;
    const float kh = 0.5f * fabsf(le[b]);   // coc = kh * |2*disp|
    const int tx = threadIdx.x;              // 0..31
    const int ty = threadIdx.y;              // 0..7
    const int tid = ty * 32 + tx;
    const int x0 = blockIdx.x * TILE - RAD;
    const int y0 = blockIdx.y * TILE - RAD;

    const float* pr = xin + (size_t)(b * 4 + 0) * (H_ * W_);
    const float* pg = xin + (size_t)(b * 4 + 1) * (H_ * W_);
    const float* pb = xin + (size_t)(b * 4 + 2) * (H_ * W_);
    const float* pd = xin + (size_t)(b * 4 + 3) * (H_ * W_);

    // Cooperative tile load with edge-clamp (matches jnp.pad mode='edge')
    for (int i = tid; i < SH * SH; i += NTHREADS) {
        int ly = i / SH;
        int lx = i - ly * SH;
        int gy = min(max(y0 + ly, 0), H_ - 1);
        int gx = min(max(x0 + lx, 0), W_ - 1);
        int gi = gy * W_ + gx;
        sh[i] = make_float4(pr[gi], pg[gi], pb[gi], 2.0f * pd[gi]);
    }
    __syncthreads();

    // CT[n] = sqrt(n) - 0.5, n = oy^2+ox^2 (compile-time folded)
    constexpr float CT[31] = {
        -0.5f,       0.5f,        0.91421356f, 0.f,         1.5f,
         1.73606798f, 0.f,        0.f,         2.32842712f, 2.5f,
         2.66227766f, 0.f,        0.f,         3.10555128f, 0.f,
         0.f,         3.5f,       3.62310563f, 3.74264069f, 0.f,
         3.97213595f, 0.f,        0.f,         0.f,         0.f,
         4.5f,        4.59901951f,0.f,         0.f,         4.88516481f,
         0.f };

    // This thread's 4 dest pixels: rows ty*V .. ty*V+3 of the tile
    const int syb = ty * V + RAD;             // shared row of dest k=0
    const int sxb = tx + RAD;
    const float4* dst0 = &sh[syb * SH + sxb];

    float eq[V];
    #pragma unroll
    for (int k = 0; k < V; k++) eq[k] = dst0[k * SH].w;   // 2*disp at dests

    uint64_t acc_rg[V], acc_bd[V];
    #pragma unroll
    for (int k = 0; k < V; k++) { acc_rg[k] = 0ull; acc_bd[k] = 0ull; }

    #pragma unroll
    for (int sr = -RAD; sr <= RAD + V - 1; sr++) {
        // min over k of (sr-k)^2 — compile-time
        const int d0 = sr * sr, d1 = (sr-1)*(sr-1), d2 = (sr-2)*(sr-2), d3 = (sr-3)*(sr-3);
        const int minsq = min(min(d0, d1), min(d2, d3));
        const float4* rowp = dst0 + sr * SH;

        #pragma unroll
        for (int ox = -RAD; ox <= RAD; ox++) {
            if (ox * ox + minsq > 30) continue;           // no dest uses this tap
            float4 s = rowp[ox];                          // one LDS.128, 4 dests
            float coc = kh * fabsf(s.w);
            uint64_t rg = pk2(s.x, s.y);
            uint64_t b1 = pk2(s.z, 1.0f);

            #pragma unroll
            for (int k = 0; k < V; k++) {
                const int oy = sr - k;
                if (oy < -RAD || oy > RAD) continue;
                const int n = oy * oy + ox * ox;
                if (n > 30) continue;                     // disk mask
                float w0 = __saturatef(coc - CT[n]);      // sat(coc - dist + 0.5)
                float th = tanh_fast(s.w - eq[k]);        // tanh(2*(sd-sq))
                float w  = fmaf(w0, th, w0);              // = 2*w0*sigmoid(4*(sd-sq))
                uint64_t w2 = pk2(w, w);
                fma2(acc_rg[k], w2, rg);
                fma2(acc_bd[k], w2, b1);
            }
        }
    }

    const int gx_out = blockIdx.x * TILE + tx;
    const int gy0    = blockIdx.y * TILE + ty * V;
    #pragma unroll
    for (int k = 0; k < V; k++) {
        float nr, ng, nb, dn;
        unpk2(acc_rg[k], nr, ng);
        unpk2(acc_bd[k], nb, dn);
        float inv = 1.0f / (dn + 2e-8f);                  // weights doubled -> 2*eps
        size_t o = ((size_t)(b * 3) * H_ + gy0 + k) * W_ + gx_out;
        out[o]               = nr * inv;
        out[o + H_ * W_]     = ng * inv;
        out[o + 2 * H_ * W_] = nb * inv;
    }
}

extern "C" void kernel_launch(void* const* d_in, const int* in_sizes, int n_in,
                              void* d_out, int out_size) {
    const float* x  = (const float*)d_in[0];   // (4,4,1024,1024) f32
    const float* le = (const float*)d_in[1];   // (4,1) f32
    // d_in[2] (diskernel) and d_in[3] (lens_mask) are pure functions of LENS=11,
    // baked in as compile-time constants.
    dim3 grid(W_ / TILE, H_ / TILE, 4);
    dim3 blk(32, 8);
    dof_kernel<<<grid, blk>>>(x, le, (float*)d_out);
}